// round 15
// baseline (speedup 1.0000x reference)
#include <cuda_runtime.h>
#include <cuda_bf16.h>

#define G_MAX 128
#define BLOCK 128

// Lane pairs (2k, 2k+1) share one proposal: even lane scans g in [0, G/2),
// odd lane scans [G/2, G); merged with one shfl + exact compare.
// gt boxes stored INTERLEAVED (orig g = half*G/2 + k -> slot 2k+half): the two
// distinct LDS.128 addresses per warp are 16 B apart -> disjoint banks ->
// conflict-free (verified R13: L1 65% -> 38%).
// __launch_bounds__(128, 16) forces ptxas to 32 regs (same math compiled at 32
// in R11/R12) -> 64-warp ceiling instead of 52, shrinking the wave tail.
__global__ __launch_bounds__(BLOCK, 16)
void roi_match_kernel(const float4* __restrict__ props,
                      const float4* __restrict__ gt,
                      const int*    __restrict__ gtl32,   // gt labels, i32 or i64 (auto-detect)
                      float*        __restrict__ out_labels,
                      float4*       __restrict__ out_boxes,
                      int N, int G)
{
    __shared__ float4 s_gti[G_MAX];      // interleaved boxes: slot 2k+half
    __shared__ float  s_area2[2][68];    // per-half areas; 16 B pad de-conflicts
    __shared__ float4 s_gt[G_MAX];       // original order (output gather)
    __shared__ float  s_lab[G_MAX];

    const int t = threadIdx.x;
    const int Gh = G >> 1;
    if (t < G) {
        float4 b = gt[t];
        s_gt[t] = b;
        const int h = t / Gh, k = t % Gh;
        s_gti[(k << 1) | h] = b;
        s_area2[h][k] = __fmul_rn(__fsub_rn(b.z, b.x), __fsub_rn(b.w, b.y));
        // labels >= 1, so little-endian i64 => word 1 (hi word of elem 0) == 0
        int is64 = (gtl32[1] == 0) ? 1 : 0;
        s_lab[t] = (float)gtl32[is64 ? (2 * t) : t];
    }
    __syncthreads();

    const int half = t & 1;
    const int n    = blockIdx.x * (BLOCK / 2) + (t >> 1);
    const int ni   = (n < N) ? n : (N - 1);          // clamp tail loads; store guarded

    const float4 p = props[ni];
    const float parea = __fmul_rn(__fsub_rn(p.z, p.x), __fsub_rn(p.w, p.y));
    const float* __restrict__ a2 = s_area2[half];    // hoisted base (reg pressure)

    // Sentinel (bestI=0, bestS=1): only strictly-positive inter can win; an
    // all-zero row resolves to idx 0, iou = 0/(1-0) = 0 -> label -1, box gt[0],
    // matching jnp.argmax-of-zeros.
    float bestI = 0.0f, bestS = 1.0f;
    const int gs = half * Gh;
    int bestIdx = gs;

    // Gh assumed multiple of 4 (G % 8 == 0; checked on host).
    #pragma unroll 4
    for (int q = 0; q < (G >> 3); ++q) {
        // one conflict-free LDS.128 per 4 areas (even/odd bases 272 B apart)
        const float4 av = *(const float4*)&a2[q << 2];
        const float areas[4] = { av.x, av.y, av.z, av.w };
        #pragma unroll
        for (int j = 0; j < 4; ++j) {
            const int k = (q << 2) + j;
            const float4 gb = s_gti[(k << 1) | half];   // conflict-free slot
            float x1 = fmaxf(gb.x, p.x);
            float y1 = fmaxf(gb.y, p.y);
            float x2 = fminf(gb.z, p.z);
            float y2 = fminf(gb.w, p.w);
            float dx = fmaxf(__fsub_rn(x2, x1), 0.0f);
            float dy = __fsub_rn(y2, y1);               // UNclamped (see proof)
            // inter' = max(dx,0)*dy. If dy<0: inter' <= 0 -> d <= 0 -> never
            // taken (bestI>=0, S>0; at sentinel fl(neg*1) < 0). If taken,
            // inter' > 0 forces dy > 0, so inter' equals the reference's
            // clamped inter bitwise.
            float inter = __fmul_rn(dx, dy);
            float S     = __fadd_rn(areas[j], parea);   // area_g + parea
            // iou = inter/(S - inter) monotone in inter/S (S > 0):
            //   i1/(S1-i1) > i2/(S2-i2)  <=>  i1*S2 > i2*S1  (cross terms cancel)
            // FFMA sign of the cross-difference (~1 ulp of exact); strict >
            // keeps the earlier index (jnp.argmax first-max semantics).
            float d = __fmaf_rn(inter, bestS, -__fmul_rn(bestI, S));
            bool take = d > 0.0f;
            bestI   = take ? inter  : bestI;
            bestS   = take ? S      : bestS;
            bestIdx = take ? gs + k : bestIdx;
        }
    }

    // Pair merge: take partner iff strictly greater; the even lane holds the
    // lower g range, so ties keep the smaller index. Even lane stores.
    float oI   = __shfl_xor_sync(0xffffffffu, bestI, 1);
    float oS   = __shfl_xor_sync(0xffffffffu, bestS, 1);
    int   oIdx = __shfl_xor_sync(0xffffffffu, bestIdx, 1);
    float dm = __fmaf_rn(oI, bestS, -__fmul_rn(bestI, oS));
    if (dm > 0.0f) { bestI = oI; bestS = oS; bestIdx = oIdx; }

    if (half == 0 && n < N) {
        // uni = fl(bestS - bestI) == reference's fl(fl(a1+a2) - inter);
        // single IEEE division -> bitwise-equal iou for the winning pair.
        float uni = __fsub_rn(bestS, bestI);
        float iou = __fdiv_rn(bestI, uni);
        float lab = s_lab[bestIdx];
        if (iou < 0.5f) lab = (iou >= 0.1f) ? 0.0f : -1.0f;
        if (out_labels) out_labels[n] = lab;
        if (out_boxes)  out_boxes[n]  = s_gt[bestIdx];
    }
}

// Generic fallback (R4 logic) for shapes the fast path doesn't cover.
__global__ __launch_bounds__(256)
void roi_dense_kernel(const float4* __restrict__ props,
                      const float4* __restrict__ gt,
                      const int*    __restrict__ gtl32,
                      float*        __restrict__ out_labels,
                      float4*       __restrict__ out_boxes,
                      int N, int G)
{
    __shared__ float4 s_gt[G_MAX];
    __shared__ float  s_area[G_MAX];
    __shared__ float  s_lab[G_MAX];
    const int t = threadIdx.x;
    if (t < G && t < G_MAX) {
        float4 b = gt[t];
        s_gt[t]   = b;
        s_area[t] = __fmul_rn(__fsub_rn(b.z, b.x), __fsub_rn(b.w, b.y));
        int is64 = (G >= 2 && gtl32[1] == 0) ? 1 : 0;
        s_lab[t] = (float)gtl32[is64 ? (2 * t) : t];
    }
    __syncthreads();
    const int n  = blockIdx.x * 256 + t;
    const int ni = (n < N) ? n : (N - 1);
    const float4 p = props[ni];
    const float parea = __fmul_rn(__fsub_rn(p.z, p.x), __fsub_rn(p.w, p.y));
    float bestI = 0.0f, bestS = 1.0f;
    int bestIdx = 0;
    for (int g = 0; g < G; ++g) {
        const float4 gb = s_gt[g];
        float x1 = fmaxf(gb.x, p.x), y1 = fmaxf(gb.y, p.y);
        float x2 = fminf(gb.z, p.z), y2 = fminf(gb.w, p.w);
        float dx = fmaxf(__fsub_rn(x2, x1), 0.0f);
        float dy = fmaxf(__fsub_rn(y2, y1), 0.0f);
        float inter = __fmul_rn(dx, dy);
        float S     = __fadd_rn(s_area[g], parea);
        float d = __fmaf_rn(inter, bestS, -__fmul_rn(bestI, S));
        bool take = d > 0.0f;
        bestI = take ? inter : bestI;
        bestS = take ? S : bestS;
        bestIdx = take ? g : bestIdx;
    }
    if (n < N) {
        float uni = __fsub_rn(bestS, bestI);
        float iou = __fdiv_rn(bestI, uni);
        float lab = s_lab[bestIdx];
        if (iou < 0.5f) lab = (iou >= 0.1f) ? 0.0f : -1.0f;
        if (out_labels) out_labels[n] = lab;
        if (out_boxes)  out_boxes[n]  = s_gt[bestIdx];
    }
}

extern "C" void kernel_launch(void* const* d_in, const int* in_sizes, int n_in,
                              void* d_out, int out_size)
{
    const float4* props = (const float4*)d_in[0];
    const float4* gt    = (const float4*)d_in[1];
    const int*    gtl   = (const int*)d_in[2];

    const int N = in_sizes[0] / 4;
    const int G = in_sizes[1] / 4;

    float*  out       = (float*)d_out;
    float*  out_label = nullptr;
    float4* out_boxes = nullptr;
    if (out_size == 5 * N) {            // [labels (N) ; boxes (4N)] as f32
        out_label = out;
        out_boxes = (float4*)(out + N); // 16B-aligned since N % 4 == 0
    } else if (out_size == 4 * N) {     // boxes only
        out_boxes = (float4*)out;
    } else {                            // labels only
        out_label = out;
    }

    if (G <= G_MAX && G >= 8 && (G % 8) == 0) {
        const int props_per_block = BLOCK / 2;
        const int grid = (N + props_per_block - 1) / props_per_block;
        roi_match_kernel<<<grid, BLOCK>>>(props, gt, gtl, out_label, out_boxes, N, G);
    } else {
        roi_dense_kernel<<<(N + 255) / 256, 256>>>(props, gt, gtl,
                                                   out_label, out_boxes, N, G);
    }
}

// round 16
// speedup vs baseline: 1.0111x; 1.0111x over previous
#include <cuda_runtime.h>
#include <cuda_bf16.h>

#define G_MAX 128
#define BLOCK 128

// Split-2 x IPT-2: lane pairs (2k,2k+1) share TWO proposals (n0, n0+64);
// even lane scans g in [0,G/2), odd lane [G/2,G). Each gt box / area LDS is
// issued once and consumed by both proposals -> non-fp overhead per pair
// nearly halves. gt boxes stored INTERLEAVED (orig g = half*G/2+k -> slot
// 2k+half): the two distinct LDS.128 addresses per warp are 16 B apart ->
// disjoint banks -> conflict-free (verified R13: L1 65% -> 38%).
__global__ __launch_bounds__(BLOCK)
void roi_match_kernel(const float4* __restrict__ props,
                      const float4* __restrict__ gt,
                      const int*    __restrict__ gtl32,   // gt labels, i32 or i64 (auto-detect)
                      float*        __restrict__ out_labels,
                      float4*       __restrict__ out_boxes,
                      int N, int G)
{
    __shared__ float4 s_gti[G_MAX];      // interleaved boxes: slot 2k+half
    __shared__ float  s_area2[2][68];    // per-half areas; 16 B pad de-conflicts
    __shared__ float4 s_gt[G_MAX];       // original order (output gather)
    __shared__ float  s_lab[G_MAX];

    const int t = threadIdx.x;
    const int Gh = G >> 1;
    if (t < G) {
        float4 b = gt[t];
        s_gt[t] = b;
        const int h = t / Gh, k = t % Gh;
        s_gti[(k << 1) | h] = b;
        s_area2[h][k] = __fmul_rn(__fsub_rn(b.z, b.x), __fsub_rn(b.w, b.y));
        // labels >= 1, so little-endian i64 => word 1 (hi word of elem 0) == 0
        int is64 = (gtl32[1] == 0) ? 1 : 0;
        s_lab[t] = (float)gtl32[is64 ? (2 * t) : t];
    }
    __syncthreads();

    const int half = t & 1;
    const int n0   = blockIdx.x * BLOCK + (t >> 1);      // proposals n0, n0+64
    const int n1   = n0 + (BLOCK / 2);
    const int ni0  = (n0 < N) ? n0 : (N - 1);            // clamp tail loads
    const int ni1  = (n1 < N) ? n1 : (N - 1);

    const float4 p0 = props[ni0];
    const float4 p1 = props[ni1];
    const float parea0 = __fmul_rn(__fsub_rn(p0.z, p0.x), __fsub_rn(p0.w, p0.y));
    const float parea1 = __fmul_rn(__fsub_rn(p1.z, p1.x), __fsub_rn(p1.w, p1.y));
    const float* __restrict__ a2 = s_area2[half];

    // Sentinels (bestI=0, bestS=1): only strictly-positive inter can win; an
    // all-zero row resolves to idx 0 after the merge, iou = 0/(1-0) = 0 ->
    // label -1, box gt[0], matching jnp.argmax-of-zeros.
    float bI0 = 0.0f, bS0 = 1.0f, bI1 = 0.0f, bS1 = 1.0f;
    const int gs = half * Gh;
    int bX0 = gs, bX1 = gs;

    // Gh assumed multiple of 4 (G % 8 == 0; checked on host).
    #pragma unroll 2
    for (int q = 0; q < (G >> 3); ++q) {
        // one conflict-free LDS.128 per 4 areas (even/odd bases 272 B apart)
        const float4 av = *(const float4*)&a2[q << 2];
        const float areas[4] = { av.x, av.y, av.z, av.w };
        #pragma unroll
        for (int j = 0; j < 4; ++j) {
            const int k = (q << 2) + j;
            const float4 gb = s_gti[(k << 1) | half];    // one load, two pairs
            const float ag = areas[j];

            // ---- proposal 0 ----
            {
                float x1 = fmaxf(gb.x, p0.x);
                float y1 = fmaxf(gb.y, p0.y);
                float x2 = fminf(gb.z, p0.z);
                float y2 = fminf(gb.w, p0.w);
                float dx = fmaxf(__fsub_rn(x2, x1), 0.0f);
                float dy = __fsub_rn(y2, y1);            // UNclamped (see proof)
                // inter' = max(dx,0)*dy: if dy<0 then inter' <= 0 -> d <= 0 ->
                // never taken (bestI>=0, S>0; at sentinel fl(neg*1) < 0); if
                // taken, inter' > 0 forces dy > 0, so inter' equals the
                // reference's clamped inter bitwise.
                float inter = __fmul_rn(dx, dy);
                float S     = __fadd_rn(ag, parea0);     // area_g + parea
                // iou = inter/(S-inter) monotone in inter/S (S > 0):
                //   i1/(S1-i1) > i2/(S2-i2) <=> i1*S2 > i2*S1 (cross terms
                // cancel). FFMA sign of the cross-difference; strict > keeps
                // the earlier index (jnp.argmax first-max semantics).
                float d = __fmaf_rn(inter, bS0, -__fmul_rn(bI0, S));
                bool take = d > 0.0f;
                bI0 = take ? inter  : bI0;
                bS0 = take ? S      : bS0;
                bX0 = take ? gs + k : bX0;
            }
            // ---- proposal 1 ----
            {
                float x1 = fmaxf(gb.x, p1.x);
                float y1 = fmaxf(gb.y, p1.y);
                float x2 = fminf(gb.z, p1.z);
                float y2 = fminf(gb.w, p1.w);
                float dx = fmaxf(__fsub_rn(x2, x1), 0.0f);
                float dy = __fsub_rn(y2, y1);
                float inter = __fmul_rn(dx, dy);
                float S     = __fadd_rn(ag, parea1);
                float d = __fmaf_rn(inter, bS1, -__fmul_rn(bI1, S));
                bool take = d > 0.0f;
                bI1 = take ? inter  : bI1;
                bS1 = take ? S      : bS1;
                bX1 = take ? gs + k : bX1;
            }
        }
    }

    // Pair merges: take partner iff strictly greater; the even lane holds the
    // lower g range, so ties keep the smaller index. Even lane stores.
    {
        float oI = __shfl_xor_sync(0xffffffffu, bI0, 1);
        float oS = __shfl_xor_sync(0xffffffffu, bS0, 1);
        int   oX = __shfl_xor_sync(0xffffffffu, bX0, 1);
        float dm = __fmaf_rn(oI, bS0, -__fmul_rn(bI0, oS));
        if (dm > 0.0f) { bI0 = oI; bS0 = oS; bX0 = oX; }
    }
    {
        float oI = __shfl_xor_sync(0xffffffffu, bI1, 1);
        float oS = __shfl_xor_sync(0xffffffffu, bS1, 1);
        int   oX = __shfl_xor_sync(0xffffffffu, bX1, 1);
        float dm = __fmaf_rn(oI, bS1, -__fmul_rn(bI1, oS));
        if (dm > 0.0f) { bI1 = oI; bS1 = oS; bX1 = oX; }
    }

    if (half == 0) {
        // uni = fl(bestS - bestI) == reference's fl(fl(a1+a2) - inter);
        // single IEEE division -> bitwise-equal iou for the winning pair.
        if (n0 < N) {
            float uni = __fsub_rn(bS0, bI0);
            float iou = __fdiv_rn(bI0, uni);
            float lab = s_lab[bX0];
            if (iou < 0.5f) lab = (iou >= 0.1f) ? 0.0f : -1.0f;
            if (out_labels) out_labels[n0] = lab;
            if (out_boxes)  out_boxes[n0]  = s_gt[bX0];
        }
        if (n1 < N) {
            float uni = __fsub_rn(bS1, bI1);
            float iou = __fdiv_rn(bI1, uni);
            float lab = s_lab[bX1];
            if (iou < 0.5f) lab = (iou >= 0.1f) ? 0.0f : -1.0f;
            if (out_labels) out_labels[n1] = lab;
            if (out_boxes)  out_boxes[n1]  = s_gt[bX1];
        }
    }
}

// Generic fallback (R4 logic) for shapes the fast path doesn't cover.
__global__ __launch_bounds__(256)
void roi_dense_kernel(const float4* __restrict__ props,
                      const float4* __restrict__ gt,
                      const int*    __restrict__ gtl32,
                      float*        __restrict__ out_labels,
                      float4*       __restrict__ out_boxes,
                      int N, int G)
{
    __shared__ float4 s_gt[G_MAX];
    __shared__ float  s_area[G_MAX];
    __shared__ float  s_lab[G_MAX];
    const int t = threadIdx.x;
    if (t < G && t < G_MAX) {
        float4 b = gt[t];
        s_gt[t]   = b;
        s_area[t] = __fmul_rn(__fsub_rn(b.z, b.x), __fsub_rn(b.w, b.y));
        int is64 = (G >= 2 && gtl32[1] == 0) ? 1 : 0;
        s_lab[t] = (float)gtl32[is64 ? (2 * t) : t];
    }
    __syncthreads();
    const int n  = blockIdx.x * 256 + t;
    const int ni = (n < N) ? n : (N - 1);
    const float4 p = props[ni];
    const float parea = __fmul_rn(__fsub_rn(p.z, p.x), __fsub_rn(p.w, p.y));
    float bestI = 0.0f, bestS = 1.0f;
    int bestIdx = 0;
    for (int g = 0; g < G; ++g) {
        const float4 gb = s_gt[g];
        float x1 = fmaxf(gb.x, p.x), y1 = fmaxf(gb.y, p.y);
        float x2 = fminf(gb.z, p.z), y2 = fminf(gb.w, p.w);
        float dx = fmaxf(__fsub_rn(x2, x1), 0.0f);
        float dy = fmaxf(__fsub_rn(y2, y1), 0.0f);
        float inter = __fmul_rn(dx, dy);
        float S     = __fadd_rn(s_area[g], parea);
        float d = __fmaf_rn(inter, bestS, -__fmul_rn(bestI, S));
        bool take = d > 0.0f;
        bestI = take ? inter : bestI;
        bestS = take ? S : bestS;
        bestIdx = take ? g : bestIdx;
    }
    if (n < N) {
        float uni = __fsub_rn(bestS, bestI);
        float iou = __fdiv_rn(bestI, uni);
        float lab = s_lab[bestIdx];
        if (iou < 0.5f) lab = (iou >= 0.1f) ? 0.0f : -1.0f;
        if (out_labels) out_labels[n] = lab;
        if (out_boxes)  out_boxes[n]  = s_gt[bestIdx];
    }
}

extern "C" void kernel_launch(void* const* d_in, const int* in_sizes, int n_in,
                              void* d_out, int out_size)
{
    const float4* props = (const float4*)d_in[0];
    const float4* gt    = (const float4*)d_in[1];
    const int*    gtl   = (const int*)d_in[2];

    const int N = in_sizes[0] / 4;
    const int G = in_sizes[1] / 4;

    float*  out       = (float*)d_out;
    float*  out_label = nullptr;
    float4* out_boxes = nullptr;
    if (out_size == 5 * N) {            // [labels (N) ; boxes (4N)] as f32
        out_label = out;
        out_boxes = (float4*)(out + N); // 16B-aligned since N % 4 == 0
    } else if (out_size == 4 * N) {     // boxes only
        out_boxes = (float4*)out;
    } else {                            // labels only
        out_label = out;
    }

    if (G <= G_MAX && G >= 8 && (G % 8) == 0) {
        const int grid = (N + BLOCK - 1) / BLOCK;   // 128 proposals per block
        roi_match_kernel<<<grid, BLOCK>>>(props, gt, gtl, out_label, out_boxes, N, G);
    } else {
        roi_dense_kernel<<<(N + 255) / 256, 256>>>(props, gt, gtl,
                                                   out_label, out_boxes, N, G);
    }
}

// round 17
// speedup vs baseline: 1.0739x; 1.0620x over previous
#include <cuda_runtime.h>
#include <cuda_bf16.h>

#define G_MAX 128
#define BLOCK 256

// Lane pairs (2k, 2k+1) share one proposal: even lane scans g in [0, G/2),
// odd lane scans [G/2, G); merged with one shfl + exact compare.
// gt boxes stored INTERLEAVED (orig g = half*G/2 + k -> slot 2k+half): the two
// distinct LDS.128 addresses per warp are 16 B apart -> disjoint banks ->
// conflict-free (verified R13: L1 65% -> 38%). BLOCK=256 + unroll 8 are
// scheduling-shape changes only; math is bitwise identical to the R13 winner.
__global__ __launch_bounds__(BLOCK)
void roi_match_kernel(const float4* __restrict__ props,
                      const float4* __restrict__ gt,
                      const int*    __restrict__ gtl32,   // gt labels, i32 or i64 (auto-detect)
                      float*        __restrict__ out_labels,
                      float4*       __restrict__ out_boxes,
                      int N, int G)
{
    __shared__ float4 s_gti[G_MAX];      // interleaved boxes: slot 2k+half
    __shared__ float  s_area2[2][68];    // per-half areas; 16 B pad de-conflicts
    __shared__ float4 s_gt[G_MAX];       // original order (output gather)
    __shared__ float  s_lab[G_MAX];

    const int t = threadIdx.x;
    const int Gh = G >> 1;
    if (t < G) {
        float4 b = gt[t];
        s_gt[t] = b;
        const int h = t / Gh, k = t % Gh;
        s_gti[(k << 1) | h] = b;
        s_area2[h][k] = __fmul_rn(__fsub_rn(b.z, b.x), __fsub_rn(b.w, b.y));
        // labels >= 1, so little-endian i64 => word 1 (hi word of elem 0) == 0
        int is64 = (gtl32[1] == 0) ? 1 : 0;
        s_lab[t] = (float)gtl32[is64 ? (2 * t) : t];
    }
    __syncthreads();

    const int half = t & 1;
    const int n    = blockIdx.x * (BLOCK / 2) + (t >> 1);
    const int ni   = (n < N) ? n : (N - 1);          // clamp tail loads; store guarded

    const float4 p = props[ni];
    const float parea = __fmul_rn(__fsub_rn(p.z, p.x), __fsub_rn(p.w, p.y));
    const float* __restrict__ a2 = s_area2[half];

    // Sentinel (bestI=0, bestS=1): only strictly-positive inter can win; an
    // all-zero row resolves to idx 0, iou = 0/(1-0) = 0 -> label -1, box gt[0],
    // matching jnp.argmax-of-zeros.
    float bestI = 0.0f, bestS = 1.0f;
    const int gs = half * Gh;
    int bestIdx = gs;

    // Gh assumed multiple of 4 (G % 8 == 0; checked on host). unroll 8 ->
    // two area-vector loads + 8 box loads batched per branch: deeper LDS MLP
    // to cover the 29-cyc shared latency; body ~4.5 KB, fits L0 I$.
    #pragma unroll 8
    for (int q = 0; q < (G >> 3); ++q) {
        // one conflict-free LDS.128 per 4 areas (even/odd bases 272 B apart)
        const float4 av = *(const float4*)&a2[q << 2];
        const float areas[4] = { av.x, av.y, av.z, av.w };
        #pragma unroll
        for (int j = 0; j < 4; ++j) {
            const int k = (q << 2) + j;
            const float4 gb = s_gti[(k << 1) | half];   // conflict-free slot
            float x1 = fmaxf(gb.x, p.x);
            float y1 = fmaxf(gb.y, p.y);
            float x2 = fminf(gb.z, p.z);
            float y2 = fminf(gb.w, p.w);
            float dx = fmaxf(__fsub_rn(x2, x1), 0.0f);
            float dy = __fsub_rn(y2, y1);               // UNclamped (see proof)
            // inter' = max(dx,0)*dy: if dy<0 then inter' <= 0 -> d <= 0 ->
            // never taken (bestI>=0, S>0; at sentinel fl(neg*1) < 0); if
            // taken, inter' > 0 forces dy > 0, so inter' equals the
            // reference's clamped inter bitwise.
            float inter = __fmul_rn(dx, dy);
            float S     = __fadd_rn(areas[j], parea);   // area_g + parea
            // iou = inter/(S - inter) monotone in inter/S (S > 0):
            //   i1/(S1-i1) > i2/(S2-i2)  <=>  i1*S2 > i2*S1  (cross terms cancel)
            // FFMA sign of the cross-difference (~1 ulp of exact); strict >
            // keeps the earlier index (jnp.argmax first-max semantics).
            float d = __fmaf_rn(inter, bestS, -__fmul_rn(bestI, S));
            bool take = d > 0.0f;
            bestI   = take ? inter  : bestI;
            bestS   = take ? S      : bestS;
            bestIdx = take ? gs + k : bestIdx;
        }
    }

    // Pair merge: take partner iff strictly greater; the even lane holds the
    // lower g range, so ties keep the smaller index. Even lane stores.
    float oI   = __shfl_xor_sync(0xffffffffu, bestI, 1);
    float oS   = __shfl_xor_sync(0xffffffffu, bestS, 1);
    int   oIdx = __shfl_xor_sync(0xffffffffu, bestIdx, 1);
    float dm = __fmaf_rn(oI, bestS, -__fmul_rn(bestI, oS));
    if (dm > 0.0f) { bestI = oI; bestS = oS; bestIdx = oIdx; }

    if (half == 0 && n < N) {
        // uni = fl(bestS - bestI) == reference's fl(fl(a1+a2) - inter);
        // single IEEE division -> bitwise-equal iou for the winning pair.
        float uni = __fsub_rn(bestS, bestI);
        float iou = __fdiv_rn(bestI, uni);
        float lab = s_lab[bestIdx];
        if (iou < 0.5f) lab = (iou >= 0.1f) ? 0.0f : -1.0f;
        if (out_labels) out_labels[n] = lab;
        if (out_boxes)  out_boxes[n]  = s_gt[bestIdx];
    }
}

// Generic fallback (R4 logic) for shapes the fast path doesn't cover.
__global__ __launch_bounds__(256)
void roi_dense_kernel(const float4* __restrict__ props,
                      const float4* __restrict__ gt,
                      const int*    __restrict__ gtl32,
                      float*        __restrict__ out_labels,
                      float4*       __restrict__ out_boxes,
                      int N, int G)
{
    __shared__ float4 s_gt[G_MAX];
    __shared__ float  s_area[G_MAX];
    __shared__ float  s_lab[G_MAX];
    const int t = threadIdx.x;
    if (t < G && t < G_MAX) {
        float4 b = gt[t];
        s_gt[t]   = b;
        s_area[t] = __fmul_rn(__fsub_rn(b.z, b.x), __fsub_rn(b.w, b.y));
        int is64 = (G >= 2 && gtl32[1] == 0) ? 1 : 0;
        s_lab[t] = (float)gtl32[is64 ? (2 * t) : t];
    }
    __syncthreads();
    const int n  = blockIdx.x * 256 + t;
    const int ni = (n < N) ? n : (N - 1);
    const float4 p = props[ni];
    const float parea = __fmul_rn(__fsub_rn(p.z, p.x), __fsub_rn(p.w, p.y));
    float bestI = 0.0f, bestS = 1.0f;
    int bestIdx = 0;
    for (int g = 0; g < G; ++g) {
        const float4 gb = s_gt[g];
        float x1 = fmaxf(gb.x, p.x), y1 = fmaxf(gb.y, p.y);
        float x2 = fminf(gb.z, p.z), y2 = fminf(gb.w, p.w);
        float dx = fmaxf(__fsub_rn(x2, x1), 0.0f);
        float dy = fmaxf(__fsub_rn(y2, y1), 0.0f);
        float inter = __fmul_rn(dx, dy);
        float S     = __fadd_rn(s_area[g], parea);
        float d = __fmaf_rn(inter, bestS, -__fmul_rn(bestI, S));
        bool take = d > 0.0f;
        bestI = take ? inter : bestI;
        bestS = take ? S : bestS;
        bestIdx = take ? g : bestIdx;
    }
    if (n < N) {
        float uni = __fsub_rn(bestS, bestI);
        float iou = __fdiv_rn(bestI, uni);
        float lab = s_lab[bestIdx];
        if (iou < 0.5f) lab = (iou >= 0.1f) ? 0.0f : -1.0f;
        if (out_labels) out_labels[n] = lab;
        if (out_boxes)  out_boxes[n]  = s_gt[bestIdx];
    }
}

extern "C" void kernel_launch(void* const* d_in, const int* in_sizes, int n_in,
                              void* d_out, int out_size)
{
    const float4* props = (const float4*)d_in[0];
    const float4* gt    = (const float4*)d_in[1];
    const int*    gtl   = (const int*)d_in[2];

    const int N = in_sizes[0] / 4;
    const int G = in_sizes[1] / 4;

    float*  out       = (float*)d_out;
    float*  out_label = nullptr;
    float4* out_boxes = nullptr;
    if (out_size == 5 * N) {            // [labels (N) ; boxes (4N)] as f32
        out_label = out;
        out_boxes = (float4*)(out + N); // 16B-aligned since N % 4 == 0
    } else if (out_size == 4 * N) {     // boxes only
        out_boxes = (float4*)out;
    } else {                            // labels only
        out_label = out;
    }

    if (G <= G_MAX && G >= 8 && (G % 8) == 0) {
        const int props_per_block = BLOCK / 2;
        const int grid = (N + props_per_block - 1) / props_per_block;
        roi_match_kernel<<<grid, BLOCK>>>(props, gt, gtl, out_label, out_boxes, N, G);
    } else {
        roi_dense_kernel<<<(N + 255) / 256, 256>>>(props, gt, gtl,
                                                   out_label, out_boxes, N, G);
    }
}